// round 1
// baseline (speedup 1.0000x reference)
#include <cuda_runtime.h>

#define N_HID 64
#define MAXN 100000
#define MAXE 3200000
#define NGRAPH 512

// Scratch (device globals — no allocation allowed)
__device__ __align__(16) float g_dinv[MAXN];
__device__ __align__(16) float g_w[MAXE];
__device__ __align__(16) float g_A[(size_t)MAXN * N_HID];
__device__ __align__(16) float g_B[(size_t)MAXN * N_HID];
__device__ __align__(16) float g_pool[NGRAPH * N_HID];
__device__ float g_cnt[NGRAPH];

// ---------------- degree / norm ----------------
__global__ void k_set_deg(int n) {
    int i = blockIdx.x * blockDim.x + threadIdx.x;
    if (i < n) g_dinv[i] = 1.0f;  // self-loop counts as 1
}

__global__ void k_add_deg(const int* __restrict__ dst, int E) {
    int e = blockIdx.x * blockDim.x + threadIdx.x;
    if (e < E) atomicAdd(&g_dinv[dst[e]], 1.0f);
}

__global__ void k_rsqrt_deg(int n) {
    int i = blockIdx.x * blockDim.x + threadIdx.x;
    if (i < n) g_dinv[i] = rsqrtf(g_dinv[i]);
}

__global__ void k_edge_w(const int* __restrict__ src, const int* __restrict__ dst, int E) {
    int e = blockIdx.x * blockDim.x + threadIdx.x;
    if (e < E) g_w[e] = g_dinv[src[e]] * g_dinv[dst[e]];
}

// ---------------- GEMM: H[n][64] = act(X[n][K]) @ W[K][64] ----------------
// act = PRE ? relu(x + pb[k]) : x   (fuses previous layer's bias+relu)
template <int K, bool PRE>
__global__ void __launch_bounds__(256) k_gemm(const float* __restrict__ X,
                                              const float* __restrict__ W,
                                              const float* __restrict__ pb,
                                              float* __restrict__ H, int n) {
    __shared__ float Ws[64][64];
    __shared__ float Xs[64][64];
    const int row0 = blockIdx.x * 64;
    const int tx = threadIdx.x & 15;   // 16 col-threads * 4 cols = 64
    const int ty = threadIdx.x >> 4;   // 16 row-threads * 4 rows = 64
    float acc[4][4] = {};

    for (int k0 = 0; k0 < K; k0 += 64) {
        for (int i = threadIdx.x; i < 64 * 64; i += 256) {
            int k = i >> 6, c = i & 63;
            Ws[k][c] = W[(size_t)(k0 + k) * 64 + c];
        }
        for (int i = threadIdx.x; i < 64 * 64; i += 256) {
            int r = i >> 6, k = i & 63;
            int row = row0 + r;
            float v = 0.0f;
            if (row < n) {
                v = X[(size_t)row * K + k0 + k];
                if (PRE) v = fmaxf(v + pb[k0 + k], 0.0f);
            }
            Xs[r][k] = v;
        }
        __syncthreads();
#pragma unroll
        for (int k = 0; k < 64; k++) {
            float4 wv = *(const float4*)&Ws[k][tx * 4];
            float x0 = Xs[ty * 4 + 0][k];
            float x1 = Xs[ty * 4 + 1][k];
            float x2 = Xs[ty * 4 + 2][k];
            float x3 = Xs[ty * 4 + 3][k];
            acc[0][0] += x0 * wv.x; acc[0][1] += x0 * wv.y; acc[0][2] += x0 * wv.z; acc[0][3] += x0 * wv.w;
            acc[1][0] += x1 * wv.x; acc[1][1] += x1 * wv.y; acc[1][2] += x1 * wv.z; acc[1][3] += x1 * wv.w;
            acc[2][0] += x2 * wv.x; acc[2][1] += x2 * wv.y; acc[2][2] += x2 * wv.z; acc[2][3] += x2 * wv.w;
            acc[3][0] += x3 * wv.x; acc[3][1] += x3 * wv.y; acc[3][2] += x3 * wv.z; acc[3][3] += x3 * wv.w;
        }
        __syncthreads();
    }
#pragma unroll
    for (int i = 0; i < 4; i++) {
        int row = row0 + ty * 4 + i;
        if (row < n) {
            float4 o = make_float4(acc[i][0], acc[i][1], acc[i][2], acc[i][3]);
            *(float4*)&H[(size_t)row * 64 + tx * 4] = o;
        }
    }
}

// ---------------- init out with self-loop contribution ----------------
__global__ void k_selfloop(const float* __restrict__ Hin, float* __restrict__ Hout, int n) {
    int idx = blockIdx.x * blockDim.x + threadIdx.x;
    int i = idx >> 4, c = idx & 15;
    if (i >= n) return;
    float d = g_dinv[i];
    float s = d * d;
    float4 h = *(const float4*)&Hin[(size_t)i * 64 + c * 4];
    float4 o = make_float4(h.x * s, h.y * s, h.z * s, h.w * s);
    *(float4*)&Hout[(size_t)i * 64 + c * 4] = o;
}

// ---------------- edge scatter: Hout[dst] += w[e] * Hin[src] ----------------
__device__ __forceinline__ void red_add_v4(float* p, float a, float b, float c, float d) {
    unsigned long long gp;
    asm("cvta.to.global.u64 %0, %1;" : "=l"(gp) : "l"(p));
    asm volatile("red.global.add.v4.f32 [%0], {%1, %2, %3, %4};"
                 :: "l"(gp), "f"(a), "f"(b), "f"(c), "f"(d) : "memory");
}

__global__ void k_scatter(const int* __restrict__ src, const int* __restrict__ dst,
                          const float* __restrict__ Hin, float* __restrict__ Hout, int E) {
    long long idx = (long long)blockIdx.x * blockDim.x + threadIdx.x;
    int e = (int)(idx >> 4);
    int c = (int)(idx & 15);
    if (e >= E) return;
    int s = src[e];
    int d = dst[e];
    float we = g_w[e];
    float4 h = *(const float4*)&Hin[(size_t)s * 64 + c * 4];
    red_add_v4(&Hout[(size_t)d * 64 + c * 4], h.x * we, h.y * we, h.z * we, h.w * we);
}

// ---------------- pooling ----------------
__global__ void k_zero_pool() {
    int i = blockIdx.x * blockDim.x + threadIdx.x;
    if (i < NGRAPH * N_HID) g_pool[i] = 0.0f;
    if (i < NGRAPH) g_cnt[i] = 0.0f;
}

__global__ void k_pool(const float* __restrict__ H, const float* __restrict__ b3,
                       const int* __restrict__ batch, int n) {
    int idx = blockIdx.x * blockDim.x + threadIdx.x;
    int i = idx >> 4, c = idx & 15;
    if (i >= n) return;
    int g = batch[i];
    float4 h = *(const float4*)&H[(size_t)i * 64 + c * 4];
    float4 bb = *(const float4*)&b3[c * 4];
    h.x = fmaxf(h.x + bb.x, 0.0f);
    h.y = fmaxf(h.y + bb.y, 0.0f);
    h.z = fmaxf(h.z + bb.z, 0.0f);
    h.w = fmaxf(h.w + bb.w, 0.0f);
    red_add_v4(&g_pool[g * 64 + c * 4], h.x, h.y, h.z, h.w);
    if (c == 0) atomicAdd(&g_cnt[g], 1.0f);
}

// ---------------- classifier head ----------------
__global__ void k_classifier(const float* __restrict__ Wc1, const float* __restrict__ bc1,
                             const float* __restrict__ Wc2, const float* __restrict__ bc2,
                             float* __restrict__ out) {
    __shared__ float p[64];
    __shared__ float z[32];
    int g = blockIdx.x;
    int t = threadIdx.x;  // 32 threads
    float inv = 1.0f / fmaxf(g_cnt[g], 1.0f);
    p[t] = g_pool[g * 64 + t] * inv;
    p[t + 32] = g_pool[g * 64 + 32 + t] * inv;
    __syncwarp();
    float acc = bc1[t];
#pragma unroll
    for (int k = 0; k < 64; k++) acc += p[k] * Wc1[k * 32 + t];
    z[t] = fmaxf(acc, 0.0f);
    __syncwarp();
    if (t < 10) {
        float a = bc2[t];
#pragma unroll
        for (int k = 0; k < 32; k++) a += z[k] * Wc2[k * 10 + t];
        out[g * 10 + t] = a;
    }
}

extern "C" void kernel_launch(void* const* d_in, const int* in_sizes, int n_in,
                              void* d_out, int out_size) {
    const float* x    = (const float*)d_in[0];
    const int*   ei   = (const int*)d_in[1];
    const int*   bat  = (const int*)d_in[2];
    const float* W1   = (const float*)d_in[3];
    const float* b1   = (const float*)d_in[4];
    const float* W2   = (const float*)d_in[5];
    const float* b2   = (const float*)d_in[6];
    const float* W3   = (const float*)d_in[7];
    const float* b3   = (const float*)d_in[8];
    const float* Wc1  = (const float*)d_in[9];
    const float* bc1  = (const float*)d_in[10];
    const float* Wc2  = (const float*)d_in[11];
    const float* bc2  = (const float*)d_in[12];

    const int n = in_sizes[0] / 128;
    const int E = in_sizes[1] / 2;
    const int* src = ei;
    const int* dst = ei + E;

    float *dA, *dB;
    cudaGetSymbolAddress((void**)&dA, g_A);
    cudaGetSymbolAddress((void**)&dB, g_B);

    const int TB = 256;
    int gn   = (n + TB - 1) / TB;
    int gE   = (E + TB - 1) / TB;
    int gn16 = (int)(((long long)n * 16 + TB - 1) / TB);
    int gE16 = (int)(((long long)E * 16 + TB - 1) / TB);
    int gRow = (n + 63) / 64;

    // norm (layer-invariant, computed once per call)
    k_set_deg<<<gn, TB>>>(n);
    k_add_deg<<<gE, TB>>>(dst, E);
    k_rsqrt_deg<<<gn, TB>>>(n);
    k_edge_w<<<gE, TB>>>(src, dst, E);

    // layer 1: A = x @ W1 ; B = selfloop(A) + scatter(A)
    k_gemm<128, false><<<gRow, TB>>>(x, W1, nullptr, dA, n);
    k_selfloop<<<gn16, TB>>>(dA, dB, n);
    k_scatter<<<gE16, TB>>>(src, dst, dA, dB, E);

    // layer 2: A = relu(B + b1) @ W2 ; B = selfloop(A) + scatter(A)
    k_gemm<64, true><<<gRow, TB>>>(dB, W2, b1, dA, n);
    k_selfloop<<<gn16, TB>>>(dA, dB, n);
    k_scatter<<<gE16, TB>>>(src, dst, dA, dB, E);

    // layer 3: A = relu(B + b2) @ W3 ; B = selfloop(A) + scatter(A)
    k_gemm<64, true><<<gRow, TB>>>(dB, W3, b2, dA, n);
    k_selfloop<<<gn16, TB>>>(dA, dB, n);
    k_scatter<<<gE16, TB>>>(src, dst, dA, dB, E);

    // mean-pool (fuses relu(B + b3)) + classifier
    k_zero_pool<<<(NGRAPH * N_HID + TB - 1) / TB, TB>>>();
    k_pool<<<gn16, TB>>>(dB, b3, bat, n);
    k_classifier<<<NGRAPH, 32>>>(Wc1, bc1, Wc2, bc2, (float*)d_out);
}

// round 2
// speedup vs baseline: 1.7321x; 1.7321x over previous
#include <cuda_runtime.h>

#define N_HID 64
#define MAXN 100000
#define MAXE 3200000
#define NGRAPH 512
#define SCAN_BLK 1024   // elements per scan1 block (256 thr * 4)
#define MAXPART 128     // >= ceil(MAXN/SCAN_BLK) = 98

// Scratch (device globals — no allocation allowed)
__device__ __align__(16) float g_dinv[MAXN];
__device__ __align__(16) int   g_cnt2[MAXN];          // per-node in-degree (excl self)
__device__ __align__(16) int   g_off[MAXN + 1];       // CSR offsets
__device__ __align__(16) int   g_cur[MAXN];           // sort cursors
__device__ __align__(16) int   g_part[MAXPART];       // scan partials
__device__ __align__(16) int2  g_elist[MAXE];         // sorted (src, w-bits) pairs
__device__ __align__(16) float g_A[(size_t)MAXN * N_HID];
__device__ __align__(16) float g_B[(size_t)MAXN * N_HID];
__device__ __align__(16) float g_pool[NGRAPH * N_HID];
__device__ float g_cnt[NGRAPH];

// ---------------- histogram of dst ----------------
__global__ void k_zero_cnt(int n) {
    int i = blockIdx.x * blockDim.x + threadIdx.x;
    if (i < n) g_cnt2[i] = 0;
}

__global__ void k_hist(const int* __restrict__ dst, int E) {
    int e = blockIdx.x * blockDim.x + threadIdx.x;
    if (e < E) atomicAdd(&g_cnt2[dst[e]], 1);
}

// ---------------- exclusive scan (3 kernels) ----------------
__global__ void __launch_bounds__(256) k_scan1(int n) {
    __shared__ int wt[8];
    __shared__ int wtex[8];
    const int t = threadIdx.x, lane = t & 31, warp = t >> 5;
    const int base = blockIdx.x * SCAN_BLK + t * 4;
    int a0 = (base + 0 < n) ? g_cnt2[base + 0] : 0;
    int a1 = (base + 1 < n) ? g_cnt2[base + 1] : 0;
    int a2 = (base + 2 < n) ? g_cnt2[base + 2] : 0;
    int a3 = (base + 3 < n) ? g_cnt2[base + 3] : 0;
    int sum4 = a0 + a1 + a2 + a3;
    int v = sum4;
#pragma unroll
    for (int o = 1; o < 32; o <<= 1) {
        int u = __shfl_up_sync(0xFFFFFFFFu, v, o);
        if (lane >= o) v += u;
    }
    if (lane == 31) wt[warp] = v;
    __syncthreads();
    if (t == 0) {
        int run = 0;
#pragma unroll
        for (int w = 0; w < 8; w++) { wtex[w] = run; run += wt[w]; }
        g_part[blockIdx.x] = run;
    }
    __syncthreads();
    int ex = v - sum4 + wtex[warp];
    if (base + 0 < n) g_off[base + 0] = ex;
    if (base + 1 < n) g_off[base + 1] = ex + a0;
    if (base + 2 < n) g_off[base + 2] = ex + a0 + a1;
    if (base + 3 < n) g_off[base + 3] = ex + a0 + a1 + a2;
}

__global__ void k_scan2(int nb) {
    if (threadIdx.x == 0) {
        int run = 0;
        for (int i = 0; i < nb; i++) { int c = g_part[i]; g_part[i] = run; run += c; }
    }
}

__global__ void k_scan3(int n, int E) {
    int i = blockIdx.x * blockDim.x + threadIdx.x;
    if (i < n) g_off[i] += g_part[i >> 10];
    if (i == 0) g_off[n] = E;
}

// ---------------- dinv + cursor reset ----------------
__global__ void k_dinv(int n) {
    int i = blockIdx.x * blockDim.x + threadIdx.x;
    if (i < n) {
        g_dinv[i] = rsqrtf((float)g_cnt2[i] + 1.0f);  // +1 self-loop
        g_cur[i] = 0;
    }
}

// ---------------- counting-sort edges by dst, fusing w computation ----------------
__global__ void k_sortscatter(const int* __restrict__ src, const int* __restrict__ dst, int E) {
    int e = blockIdx.x * blockDim.x + threadIdx.x;
    if (e >= E) return;
    int s = src[e];
    int d = dst[e];
    float w = g_dinv[s] * g_dinv[d];
    int r = atomicAdd(&g_cur[d], 1);
    int idx = g_off[d] + r;
    g_elist[idx] = make_int2(s, __float_as_int(w));
}

// ---------------- GEMM: H[n][64] = act(X[n][K]) @ W[K][64] ----------------
template <int K, bool PRE>
__global__ void __launch_bounds__(256) k_gemm(const float* __restrict__ X,
                                              const float* __restrict__ W,
                                              const float* __restrict__ pb,
                                              float* __restrict__ H, int n) {
    __shared__ float Ws[64][64];
    __shared__ float Xs[64][64];
    const int row0 = blockIdx.x * 64;
    const int tx = threadIdx.x & 15;
    const int ty = threadIdx.x >> 4;
    float acc[4][4] = {};

    for (int k0 = 0; k0 < K; k0 += 64) {
        for (int i = threadIdx.x; i < 64 * 64; i += 256) {
            int k = i >> 6, c = i & 63;
            Ws[k][c] = W[(size_t)(k0 + k) * 64 + c];
        }
        for (int i = threadIdx.x; i < 64 * 64; i += 256) {
            int r = i >> 6, k = i & 63;
            int row = row0 + r;
            float v = 0.0f;
            if (row < n) {
                v = X[(size_t)row * K + k0 + k];
                if (PRE) v = fmaxf(v + pb[k0 + k], 0.0f);
            }
            Xs[r][k] = v;
        }
        __syncthreads();
#pragma unroll
        for (int k = 0; k < 64; k++) {
            float4 wv = *(const float4*)&Ws[k][tx * 4];
            float x0 = Xs[ty * 4 + 0][k];
            float x1 = Xs[ty * 4 + 1][k];
            float x2 = Xs[ty * 4 + 2][k];
            float x3 = Xs[ty * 4 + 3][k];
            acc[0][0] += x0 * wv.x; acc[0][1] += x0 * wv.y; acc[0][2] += x0 * wv.z; acc[0][3] += x0 * wv.w;
            acc[1][0] += x1 * wv.x; acc[1][1] += x1 * wv.y; acc[1][2] += x1 * wv.z; acc[1][3] += x1 * wv.w;
            acc[2][0] += x2 * wv.x; acc[2][1] += x2 * wv.y; acc[2][2] += x2 * wv.z; acc[2][3] += x2 * wv.w;
            acc[3][0] += x3 * wv.x; acc[3][1] += x3 * wv.y; acc[3][2] += x3 * wv.z; acc[3][3] += x3 * wv.w;
        }
        __syncthreads();
    }
#pragma unroll
    for (int i = 0; i < 4; i++) {
        int row = row0 + ty * 4 + i;
        if (row < n) {
            float4 o = make_float4(acc[i][0], acc[i][1], acc[i][2], acc[i][3]);
            *(float4*)&H[(size_t)row * 64 + tx * 4] = o;
        }
    }
}

// ---------------- gather-only aggregation: warp per dst node ----------------
// Hout[i] = dinv[i]^2 * Ain[i] + sum_j w_j * Ain[src_j]
__global__ void __launch_bounds__(256) k_gather(const float* __restrict__ Ain,
                                                float* __restrict__ Hout, int n) {
    int wid = (blockIdx.x * blockDim.x + threadIdx.x) >> 5;
    if (wid >= n) return;
    const int lane = threadIdx.x & 31;
    const int beg = g_off[wid];
    const int end = g_off[wid + 1];

    float dv = g_dinv[wid];
    float2 a = *(const float2*)(Ain + (size_t)wid * 64 + lane * 2);
    float2 acc = make_float2(a.x * dv * dv, a.y * dv * dv);

    int j = beg;
    for (; j + 4 <= end; j += 4) {
        int2 p0 = g_elist[j + 0];
        int2 p1 = g_elist[j + 1];
        int2 p2 = g_elist[j + 2];
        int2 p3 = g_elist[j + 3];
        float2 v0 = *(const float2*)(Ain + (size_t)p0.x * 64 + lane * 2);
        float2 v1 = *(const float2*)(Ain + (size_t)p1.x * 64 + lane * 2);
        float2 v2 = *(const float2*)(Ain + (size_t)p2.x * 64 + lane * 2);
        float2 v3 = *(const float2*)(Ain + (size_t)p3.x * 64 + lane * 2);
        float w0 = __int_as_float(p0.y), w1 = __int_as_float(p1.y);
        float w2 = __int_as_float(p2.y), w3 = __int_as_float(p3.y);
        acc.x += w0 * v0.x; acc.y += w0 * v0.y;
        acc.x += w1 * v1.x; acc.y += w1 * v1.y;
        acc.x += w2 * v2.x; acc.y += w2 * v2.y;
        acc.x += w3 * v3.x; acc.y += w3 * v3.y;
    }
    for (; j < end; j++) {
        int2 p = g_elist[j];
        float2 v = *(const float2*)(Ain + (size_t)p.x * 64 + lane * 2);
        float w = __int_as_float(p.y);
        acc.x += w * v.x; acc.y += w * v.y;
    }
    *(float2*)(Hout + (size_t)wid * 64 + lane * 2) = acc;
}

// ---------------- pooling ----------------
__device__ __forceinline__ void red_add_v4(float* p, float a, float b, float c, float d) {
    unsigned long long gp;
    asm("cvta.to.global.u64 %0, %1;" : "=l"(gp) : "l"(p));
    asm volatile("red.global.add.v4.f32 [%0], {%1, %2, %3, %4};"
                 :: "l"(gp), "f"(a), "f"(b), "f"(c), "f"(d) : "memory");
}

__global__ void k_zero_pool() {
    int i = blockIdx.x * blockDim.x + threadIdx.x;
    if (i < NGRAPH * N_HID) g_pool[i] = 0.0f;
    if (i < NGRAPH) g_cnt[i] = 0.0f;
}

__global__ void k_pool(const float* __restrict__ H, const float* __restrict__ b3,
                       const int* __restrict__ batch, int n) {
    int idx = blockIdx.x * blockDim.x + threadIdx.x;
    int i = idx >> 4, c = idx & 15;
    if (i >= n) return;
    int g = batch[i];
    float4 h = *(const float4*)&H[(size_t)i * 64 + c * 4];
    float4 bb = *(const float4*)&b3[c * 4];
    h.x = fmaxf(h.x + bb.x, 0.0f);
    h.y = fmaxf(h.y + bb.y, 0.0f);
    h.z = fmaxf(h.z + bb.z, 0.0f);
    h.w = fmaxf(h.w + bb.w, 0.0f);
    red_add_v4(&g_pool[g * 64 + c * 4], h.x, h.y, h.z, h.w);
    if (c == 0) atomicAdd(&g_cnt[g], 1.0f);
}

// ---------------- classifier head ----------------
__global__ void k_classifier(const float* __restrict__ Wc1, const float* __restrict__ bc1,
                             const float* __restrict__ Wc2, const float* __restrict__ bc2,
                             float* __restrict__ out) {
    __shared__ float p[64];
    __shared__ float z[32];
    int g = blockIdx.x;
    int t = threadIdx.x;  // 32 threads
    float inv = 1.0f / fmaxf(g_cnt[g], 1.0f);
    p[t] = g_pool[g * 64 + t] * inv;
    p[t + 32] = g_pool[g * 64 + 32 + t] * inv;
    __syncwarp();
    float acc = bc1[t];
#pragma unroll
    for (int k = 0; k < 64; k++) acc += p[k] * Wc1[k * 32 + t];
    z[t] = fmaxf(acc, 0.0f);
    __syncwarp();
    if (t < 10) {
        float a = bc2[t];
#pragma unroll
        for (int k = 0; k < 32; k++) a += z[k] * Wc2[k * 10 + t];
        out[g * 10 + t] = a;
    }
}

extern "C" void kernel_launch(void* const* d_in, const int* in_sizes, int n_in,
                              void* d_out, int out_size) {
    const float* x    = (const float*)d_in[0];
    const int*   ei   = (const int*)d_in[1];
    const int*   bat  = (const int*)d_in[2];
    const float* W1   = (const float*)d_in[3];
    const float* b1   = (const float*)d_in[4];
    const float* W2   = (const float*)d_in[5];
    const float* b2   = (const float*)d_in[6];
    const float* W3   = (const float*)d_in[7];
    const float* b3   = (const float*)d_in[8];
    const float* Wc1  = (const float*)d_in[9];
    const float* bc1  = (const float*)d_in[10];
    const float* Wc2  = (const float*)d_in[11];
    const float* bc2  = (const float*)d_in[12];

    const int n = in_sizes[0] / 128;
    const int E = in_sizes[1] / 2;
    const int* src = ei;
    const int* dst = ei + E;

    float *dA, *dB;
    cudaGetSymbolAddress((void**)&dA, g_A);
    cudaGetSymbolAddress((void**)&dB, g_B);

    const int TB = 256;
    int gn  = (n + TB - 1) / TB;
    int gE  = (E + TB - 1) / TB;
    int gn16 = (int)(((long long)n * 16 + TB - 1) / TB);
    int gW  = (int)(((long long)n * 32 + TB - 1) / TB);   // warp per node
    int gRow = (n + 63) / 64;
    int nb = (n + SCAN_BLK - 1) / SCAN_BLK;

    // ---- build CSR by dst + norms (once per call, reused by all 3 layers) ----
    k_zero_cnt<<<gn, TB>>>(n);
    k_hist<<<gE, TB>>>(dst, E);
    k_scan1<<<nb, 256>>>(n);
    k_scan2<<<1, 32>>>(nb);
    k_scan3<<<gn, TB>>>(n, E);
    k_dinv<<<gn, TB>>>(n);
    k_sortscatter<<<gE, TB>>>(src, dst, E);

    // layer 1: A = x @ W1 ; B = aggregate(A)
    k_gemm<128, false><<<gRow, TB>>>(x, W1, nullptr, dA, n);
    k_gather<<<gW, TB>>>(dA, dB, n);

    // layer 2: A = relu(B + b1) @ W2 ; B = aggregate(A)
    k_gemm<64, true><<<gRow, TB>>>(dB, W2, b1, dA, n);
    k_gather<<<gW, TB>>>(dA, dB, n);

    // layer 3: A = relu(B + b2) @ W3 ; B = aggregate(A)
    k_gemm<64, true><<<gRow, TB>>>(dB, W3, b2, dA, n);
    k_gather<<<gW, TB>>>(dA, dB, n);

    // mean-pool (fuses relu(B + b3)) + classifier
    k_zero_pool<<<(NGRAPH * N_HID + TB - 1) / TB, TB>>>();
    k_pool<<<gn16, TB>>>(dB, b3, bat, n);
    k_classifier<<<NGRAPH, 32>>>(Wc1, bc1, Wc2, bc2, (float*)d_out);
}